// round 13
// baseline (speedup 1.0000x reference)
#include <cuda_runtime.h>
#include <cuda_fp16.h>
#include <cuda_bf16.h>
#include <math.h>
#include <stdint.h>

#define NMAX 100000
#define EMAX 1600000

// Scratch (allocation-free rule: __device__ globals)
__device__ __half g_support[(size_t)NMAX * 128];
__device__ float  g_t[(size_t)NMAX * 128];
__device__ float  g_sum[4][128];
__device__ float  g_sq[4][128];
__device__ int    g_rowptr[NMAX + 1];
// Pre-split, pre-transposed weights: Wt[n][k] bf16 hi/lo planes.
// Offsets: W1t 0 (128x256), W2t 32768 (128x128), W3t 49152 (64x128), W4t 57344 (32x64)
__device__ __nv_bfloat16 g_wth[61440];
__device__ __nv_bfloat16 g_wtl[61440];

// ---------------------------------------------------------------------------
__global__ void zero_stats_kernel() {
    int i = threadIdx.x;
    if (i < 128) {
        #pragma unroll
        for (int l = 0; l < 4; l++) { g_sum[l][i] = 0.f; g_sq[l][i] = 0.f; }
    }
}

// ---------------------------------------------------------------------------
// CSR row_ptr from sorted adj_row via binary search (lower_bound of r).
__global__ void rowptr_kernel(const int* __restrict__ adj_row, int N, int E) {
    int r = blockIdx.x * blockDim.x + threadIdx.x;
    if (r > N) return;
    int lo = 0, hi = E;
    while (lo < hi) {
        int mid = (lo + hi) >> 1;
        if (adj_row[mid] < r) lo = mid + 1; else hi = mid;
    }
    g_rowptr[r] = lo;
}

// ---------------------------------------------------------------------------
// Split ALL FOUR W[k][n] into bf16 hi/lo, transposed to Wt[n][k]. One launch.
__global__ void wsplit_all_kernel(const float* __restrict__ W1,
                                  const float* __restrict__ W2,
                                  const float* __restrict__ W3,
                                  const float* __restrict__ W4) {
    int gidx = blockIdx.x * blockDim.x + threadIdx.x;
    const float* W; int K, OUT, base, idx;
    if (gidx < 32768)       { W = W1; K = 256; OUT = 128; base = 0;     idx = gidx; }
    else if (gidx < 49152)  { W = W2; K = 128; OUT = 128; base = 32768; idx = gidx - 32768; }
    else if (gidx < 57344)  { W = W3; K = 128; OUT = 64;  base = 49152; idx = gidx - 49152; }
    else if (gidx < 59392)  { W = W4; K = 64;  OUT = 32;  base = 57344; idx = gidx - 57344; }
    else return;
    int k = idx / OUT, n = idx % OUT;      // coalesced read
    float v = W[idx];
    __nv_bfloat16 h = __float2bfloat16_rn(v);
    float l = v - __bfloat162float(h);
    g_wth[base + (size_t)n * K + k] = h;
    g_wtl[base + (size_t)n * K + k] = __float2bfloat16_rn(l);
}

// ---------------------------------------------------------------------------
__device__ __forceinline__ void mma_bf16(float c[4], const uint32_t a[4],
                                         uint32_t b0, uint32_t b1) {
    asm volatile(
        "mma.sync.aligned.m16n8k16.row.col.f32.bf16.bf16.f32 "
        "{%0,%1,%2,%3}, {%4,%5,%6,%7}, {%8,%9}, {%0,%1,%2,%3};\n"
        : "+f"(c[0]), "+f"(c[1]), "+f"(c[2]), "+f"(c[3])
        : "r"(a[0]), "r"(a[1]), "r"(a[2]), "r"(a[3]), "r"(b0), "r"(b1));
}
__device__ __forceinline__ uint32_t pack_bf2(__nv_bfloat16 lo, __nv_bfloat16 hi) {
    __nv_bfloat162 p; p.x = lo; p.y = hi;           // .x = lower 16 bits = lower k
    return *reinterpret_cast<uint32_t*>(&p);
}
__device__ __forceinline__ uint32_t smem_u32(const void* p) {
    return (uint32_t)__cvta_generic_to_shared(p);
}
__device__ __forceinline__ void ldsm_x4(uint32_t& r0, uint32_t& r1,
                                        uint32_t& r2, uint32_t& r3, uint32_t addr) {
    asm volatile("ldmatrix.sync.aligned.m8n8.x4.shared.b16 {%0,%1,%2,%3}, [%4];"
                 : "=r"(r0), "=r"(r1), "=r"(r2), "=r"(r3) : "r"(addr));
}

// ---------------------------------------------------------------------------
// Smem sizing for the double-buffered GEMM (words of 4 bytes).
template<int OUT>
struct GemmSmem {
    static constexpr int BM = 128, SW = 20, SWW = 36;
    static constexpr int STAGE_W = 2 * BM * SW + OUT * SWW;   // Ah + Al + Wc
    static constexpr int TOTAL_W = 2 * STAGE_W + 512;          // + mean/r
    static constexpr int BYTES = TOTAL_W * 4;
};

// ---------------------------------------------------------------------------
// Tensor-core bf16x3 GEMM (hi*hi + hi*lo + lo*hi), fused input-BatchNorm.
// R13: DOUBLE-BUFFERED dynamic smem -> ONE __syncthreads per K-tile.
// Iter i: reg-prefetch tile i+1; mma from buf[i&1]; STS tile i+1 into
// buf[(i+1)&1]; sync. Safe: buf[(i+1)&1]'s last readers finished before the
// sync ending iter i-1 (compute precedes STS within an iter).
// C[N,OUT] (fp16) = norm(A)[N,K] @ W[K,OUT]. BM=128, BK=32, 8 warps, 2 CTA/SM.
template<int K, int OUT, int LAYER>
__global__ __launch_bounds__(256, 2)
void gemm_tc(const float* __restrict__ A,
             const __nv_bfloat16* __restrict__ wth,
             const __nv_bfloat16* __restrict__ wtl,
             __half* __restrict__ C, float* __restrict__ Hout, int N) {
    constexpr int BM = 128, BK = 32;
    constexpr int SW = 20;     // A stride (words). LDSM rows 80B apart: distinct 16B banks mod 128
    constexpr int SWW = 36;    // W stride (words). 144B ≡ 16 mod 128: distinct
    constexpr int WARPS_M = (OUT >= 64) ? 4 : 8;
    constexpr int WARPS_N = 8 / WARPS_M;
    constexpr int WM = BM / WARPS_M;       // 32 or 16
    constexpr int WN = OUT / WARPS_N;      // 64 / 32 / 32
    constexpr int MT = WM / 16;            // 2 or 1
    constexpr int NT = WN / 8;             // 8 / 4 / 4
    constexpr int NA = (BM * BK) / (4 * 256);        // float4 A loads/thread = 4
    constexpr int WCHUNK = OUT * (BK / 8);           // uint4 (8 bf16) chunks per W tile
    constexpr int STAGE_W = GemmSmem<OUT>::STAGE_W;

    extern __shared__ uint32_t dsm[];
    float* mean_s = (float*)(dsm + 2 * STAGE_W);
    float* r_s    = mean_s + 256;

    const int tid = threadIdx.x;
    const int w = tid >> 5, lane = tid & 31;
    const int wm = (WARPS_N == 2) ? (w >> 1) : w;
    const int wn = (WARPS_N == 2) ? (w & 1) : 0;
    const int row0 = blockIdx.x * BM;
    const int li = lane & 7, lsel = lane >> 3;     // LDSM address lanes

    if (LAYER >= 0) {
        const float invN = 1.f / (float)N;
        for (int i = tid; i < K; i += 256) {
            float m = g_sum[LAYER][i] * invN;
            float var = g_sq[LAYER][i] * invN - m * m;
            mean_s[i] = m;
            r_s[i] = rsqrtf(var + 1e-5f);
        }
        __syncthreads();
    }

    float acc[MT][NT][4];
    #pragma unroll
    for (int mt = 0; mt < MT; mt++)
        #pragma unroll
        for (int nt = 0; nt < NT; nt++)
            #pragma unroll
            for (int q = 0; q < 4; q++) acc[mt][nt][q] = 0.f;

    float4 stA[NA];   // A register staging only (W loads direct in STS phase)

    auto load_tile = [&](int kb) {
        #pragma unroll
        for (int p = 0; p < NA; p++) {
            int idx = p * 256 + tid;
            int r = idx >> 3;                  // BK/4 = 8 float4 per row
            int kq = (idx & 7) * 4;
            int gr = row0 + r;
            float4 v = make_float4(0.f, 0.f, 0.f, 0.f);
            if (gr < N) {
                v = *(const float4*)(A + (size_t)gr * K + kb + kq);
                if (LAYER >= 0) {
                    int c = kb + kq;
                    v.x = (v.x - mean_s[c + 0]) * r_s[c + 0];
                    v.y = (v.y - mean_s[c + 1]) * r_s[c + 1];
                    v.z = (v.z - mean_s[c + 2]) * r_s[c + 2];
                    v.w = (v.w - mean_s[c + 3]) * r_s[c + 3];
                    *(float4*)(Hout + (size_t)gr * K + c) = v;
                }
            }
            stA[p] = v;
        }
    };
    auto store_tile = [&](int kb, int stage) {
        uint32_t* Ah32 = dsm + stage * STAGE_W;
        uint32_t* Al32 = Ah32 + BM * SW;
        uint32_t* Wc32 = Al32 + BM * SW;
        #pragma unroll
        for (int p = 0; p < NA; p++) {
            int idx = p * 256 + tid;
            int r = idx >> 3;
            int kq = (idx & 7) * 4;
            float4 v = stA[p];
            __nv_bfloat16 hx = __float2bfloat16_rn(v.x);
            __nv_bfloat16 hy = __float2bfloat16_rn(v.y);
            __nv_bfloat16 hz = __float2bfloat16_rn(v.z);
            __nv_bfloat16 hw = __float2bfloat16_rn(v.w);
            uint2 hh = make_uint2(pack_bf2(hx, hy), pack_bf2(hz, hw));
            uint2 ll = make_uint2(
                pack_bf2(__float2bfloat16_rn(v.x - __bfloat162float(hx)),
                         __float2bfloat16_rn(v.y - __bfloat162float(hy))),
                pack_bf2(__float2bfloat16_rn(v.z - __bfloat162float(hz)),
                         __float2bfloat16_rn(v.w - __bfloat162float(hw))));
            *(uint2*)&Ah32[r * SW + (kq >> 1)] = hh;
            *(uint2*)&Al32[r * SW + (kq >> 1)] = ll;
        }
        // W: direct load -> STS (L2-resident; latency hidden by co-resident CTA)
        #pragma unroll
        for (int p = 0; p < (WCHUNK + 255) / 256; p++) {
            int idx = p * 256 + tid;
            if ((WCHUNK % 256 == 0) || idx < WCHUNK) {
                int n = idx >> 2, part = idx & 3;
                uint4 hv = *(const uint4*)(wth + (size_t)n * K + kb + part * 8);
                uint4 lv = *(const uint4*)(wtl + (size_t)n * K + kb + part * 8);
                int s = part >> 1, half = part & 1;      // k16 step, b0/b1 half
                *(uint4*)&Wc32[n * SWW + s * 16 + half * 4]     = hv;
                *(uint4*)&Wc32[n * SWW + s * 16 + 8 + half * 4] = lv;
            }
        }
    };

    load_tile(0);
    store_tile(0, 0);
    __syncthreads();

    int stage = 0;
    for (int kb = 0; kb < K; kb += BK) {
        const bool last = (kb + BK >= K);
        if (!last) load_tile(kb + BK);     // prefetch next A tile into registers

        const uint32_t* Ah32 = dsm + stage * STAGE_W;
        const uint32_t* Al32 = Ah32 + BM * SW;
        const uint32_t* Wc32 = Al32 + BM * SW;

        #pragma unroll
        for (int s = 0; s < 2; s++) {                 // two k16 steps per BK=32 tile
            const int ks8 = s * 8;
            uint32_t ah[MT][4], al[MT][4];
            #pragma unroll
            for (int mt = 0; mt < MT; mt++) {
                int mrow = wm * WM + mt * 16 + (lsel & 1) * 8 + li;
                uint32_t acol = ks8 + (lsel >> 1) * 4;
                ldsm_x4(ah[mt][0], ah[mt][1], ah[mt][2], ah[mt][3],
                        smem_u32(&Ah32[mrow * SW + acol]));
                ldsm_x4(al[mt][0], al[mt][1], al[mt][2], al[mt][3],
                        smem_u32(&Al32[mrow * SW + acol]));
            }
            #pragma unroll
            for (int nt = 0; nt < NT; nt++) {
                int n = wn * WN + nt * 8 + li;
                uint32_t bh0, bh1, bl0, bl1;
                ldsm_x4(bh0, bh1, bl0, bl1,
                        smem_u32(&Wc32[n * SWW + s * 16 + lsel * 4]));
                #pragma unroll
                for (int mt = 0; mt < MT; mt++) {
                    mma_bf16(acc[mt][nt], ah[mt], bh0, bh1);  // hi*hi
                    mma_bf16(acc[mt][nt], ah[mt], bl0, bl1);  // hi*lo
                    mma_bf16(acc[mt][nt], al[mt], bh0, bh1);  // lo*hi
                }
            }
        }
        if (!last) {
            store_tile(kb + BK, stage ^ 1);
            __syncthreads();
        }
        stage ^= 1;
    }

    // Epilogue -> fp16 support. c0,c1 at (row, t*2); c2,c3 at (row+8, t*2).
    const int g = lane >> 2, t = lane & 3;
    #pragma unroll
    for (int mt = 0; mt < MT; mt++) {
        int r0 = row0 + wm * WM + mt * 16 + g;
        #pragma unroll
        for (int nt = 0; nt < NT; nt++) {
            int n = wn * WN + nt * 8 + t * 2;
            if (r0 < N)
                *(__half2*)(C + (size_t)r0 * OUT + n) =
                    __floats2half2_rn(acc[mt][nt][0], acc[mt][nt][1]);
            if (r0 + 8 < N)
                *(__half2*)(C + (size_t)(r0 + 8) * OUT + n) =
                    __floats2half2_rn(acc[mt][nt][2], acc[mt][nt][3]);
        }
    }
}

// ---------------------------------------------------------------------------
// SpMM (warp per row, CSR) over fp16 support + leaky_relu + elu fused.
// half2 coalesced gathers, 4-edge unroll (scalar metadata loads — measured
// best). fp32 accumulation; block-local BN stats.  [frozen since R8]
template<int OUT, int LAYER>
__global__ __launch_bounds__(256)
void spmm_kernel(const __half* __restrict__ support,
                 const int* __restrict__ col,
                 const float* __restrict__ vals,
                 float* __restrict__ t, int N) {
    constexpr int H2 = (OUT >= 64) ? OUT / 64 : 0;   // half2 loads/lane: 2,1,0
    constexpr int JF = (OUT >= 64) ? 2 * H2 : 1;     // fp32 outputs/lane: 4,2,1
    __shared__ float ssum[OUT], ssq[OUT];
    const int tid = threadIdx.x;
    for (int i = tid; i < OUT; i += blockDim.x) { ssum[i] = 0.f; ssq[i] = 0.f; }
    __syncthreads();

    const int lane = tid & 31;
    const int warp = tid >> 5;
    const int row = blockIdx.x * 8 + warp;

    if (row < N) {
        float acc[JF];
        #pragma unroll
        for (int j = 0; j < JF; j++) acc[j] = 0.f;

        const int s = g_rowptr[row];
        const int e = g_rowptr[row + 1];

        auto gather1 = [&](int i) {
            int c = __ldg(&col[i]);
            float v = __ldg(&vals[i]);
            const __half* p = support + (size_t)c * OUT;
            if constexpr (H2 >= 1) {
                #pragma unroll
                for (int h = 0; h < H2; h++) {
                    __half2 m = __ldg((const __half2*)p + h * 32 + lane);
                    float2 f = __half22float2(m);
                    acc[2 * h + 0] = fmaf(v, f.x, acc[2 * h + 0]);
                    acc[2 * h + 1] = fmaf(v, f.y, acc[2 * h + 1]);
                }
            } else {
                acc[0] = fmaf(v, __half2float(__ldg(p + lane)), acc[0]);
            }
        };

        int i = s;
        for (; i + 4 <= e; i += 4) {
            int c0 = __ldg(&col[i]),     c1 = __ldg(&col[i + 1]);
            int c2 = __ldg(&col[i + 2]), c3 = __ldg(&col[i + 3]);
            float v0 = __ldg(&vals[i]),     v1 = __ldg(&vals[i + 1]);
            float v2 = __ldg(&vals[i + 2]), v3 = __ldg(&vals[i + 3]);
            const __half* p0 = support + (size_t)c0 * OUT;
            const __half* p1 = support + (size_t)c1 * OUT;
            const __half* p2 = support + (size_t)c2 * OUT;
            const __half* p3 = support + (size_t)c3 * OUT;
            if constexpr (H2 >= 1) {
                __half2 m0[H2], m1[H2], m2[H2], m3[H2];
                #pragma unroll
                for (int h = 0; h < H2; h++) m0[h] = __ldg((const __half2*)p0 + h * 32 + lane);
                #pragma unroll
                for (int h = 0; h < H2; h++) m1[h] = __ldg((const __half2*)p1 + h * 32 + lane);
                #pragma unroll
                for (int h = 0; h < H2; h++) m2[h] = __ldg((const __half2*)p2 + h * 32 + lane);
                #pragma unroll
                for (int h = 0; h < H2; h++) m3[h] = __ldg((const __half2*)p3 + h * 32 + lane);
                #pragma unroll
                for (int h = 0; h < H2; h++) {
                    float2 f0 = __half22float2(m0[h]);
                    float2 f1 = __half22float2(m1[h]);
                    float2 f2 = __half22float2(m2[h]);
                    float2 f3 = __half22float2(m3[h]);
                    acc[2*h+0] = fmaf(v3, f3.x, fmaf(v2, f2.x, fmaf(v1, f1.x, fmaf(v0, f0.x, acc[2*h+0]))));
                    acc[2*h+1] = fmaf(v3, f3.y, fmaf(v2, f2.y, fmaf(v1, f1.y, fmaf(v0, f0.y, acc[2*h+1]))));
                }
            } else {
                float f0 = __half2float(__ldg(p0 + lane));
                float f1 = __half2float(__ldg(p1 + lane));
                float f2 = __half2float(__ldg(p2 + lane));
                float f3 = __half2float(__ldg(p3 + lane));
                acc[0] = fmaf(v3, f3, fmaf(v2, f2, fmaf(v1, f1, fmaf(v0, f0, acc[0]))));
            }
        }
        for (; i < e; i++) gather1(i);

        // leaky_relu(0.2) then elu; sign preserved -> single branch
        float tv[JF];
        #pragma unroll
        for (int j = 0; j < JF; j++) {
            float a = acc[j];
            tv[j] = (a > 0.f) ? a : expm1f(0.2f * a);
        }

        float* trow = t + (size_t)row * OUT;
        if constexpr (H2 >= 1) {
            #pragma unroll
            for (int h = 0; h < H2; h++) {
                int c = 64 * h + 2 * lane;
                *(float2*)(trow + c) = make_float2(tv[2*h+0], tv[2*h+1]);
                atomicAdd(&ssum[c + 0], tv[2*h+0]);
                atomicAdd(&ssum[c + 1], tv[2*h+1]);
                atomicAdd(&ssq[c + 0], tv[2*h+0] * tv[2*h+0]);
                atomicAdd(&ssq[c + 1], tv[2*h+1] * tv[2*h+1]);
            }
        } else {
            trow[lane] = tv[0];
            atomicAdd(&ssum[lane], tv[0]);
            atomicAdd(&ssq[lane], tv[0] * tv[0]);
        }
    }
    __syncthreads();
    for (int i = tid; i < OUT; i += blockDim.x) {
        atomicAdd(&g_sum[LAYER][i], ssum[i]);
        atomicAdd(&g_sq[LAYER][i], ssq[i]);
    }
}

// ---------------------------------------------------------------------------
// BatchNorm (final layer only): out = (t - mean) * rsqrt(var + eps)
template<int OUT, int LAYER>
__global__ void norm_kernel(const float* __restrict__ t, float* __restrict__ out, int N) {
    __shared__ float mean_s[OUT], r_s[OUT];
    const float invN = 1.f / (float)N;
    for (int i = threadIdx.x; i < OUT; i += blockDim.x) {
        float m = g_sum[LAYER][i] * invN;
        float var = g_sq[LAYER][i] * invN - m * m;
        mean_s[i] = m;
        r_s[i] = rsqrtf(var + 1e-5f);
    }
    __syncthreads();
    const float4* t4 = (const float4*)t;
    float4* o4 = (float4*)out;
    size_t total4 = (size_t)N * OUT / 4;
    for (size_t i = (size_t)blockIdx.x * blockDim.x + threadIdx.x; i < total4;
         i += (size_t)gridDim.x * blockDim.x) {
        int cb = (int)(i & (OUT / 4 - 1)) * 4;
        float4 v = t4[i];
        float4 r;
        r.x = (v.x - mean_s[cb + 0]) * r_s[cb + 0];
        r.y = (v.y - mean_s[cb + 1]) * r_s[cb + 1];
        r.z = (v.z - mean_s[cb + 2]) * r_s[cb + 2];
        r.w = (v.w - mean_s[cb + 3]) * r_s[cb + 3];
        o4[i] = r;
    }
}

// ---------------------------------------------------------------------------
extern "C" void kernel_launch(void* const* d_in, const int* in_sizes, int n_in,
                              void* d_out, int out_size) {
    const float* x        = (const float*)d_in[0];
    const int*   adj_row  = (const int*)d_in[1];
    const int*   adj_col  = (const int*)d_in[2];
    const float* adj_vals = (const float*)d_in[3];
    const float* W1 = (const float*)d_in[4];
    const float* W2 = (const float*)d_in[5];
    const float* W3 = (const float*)d_in[6];
    const float* W4 = (const float*)d_in[7];
    float* out = (float*)d_out;

    const int N = in_sizes[0] / 256;
    const int E = in_sizes[1];

    __half* g_support_p; cudaGetSymbolAddress((void**)&g_support_p, g_support);
    float*  g_t_p;       cudaGetSymbolAddress((void**)&g_t_p, g_t);
    __nv_bfloat16* wth;  cudaGetSymbolAddress((void**)&wth, g_wth);
    __nv_bfloat16* wtl;  cudaGetSymbolAddress((void**)&wtl, g_wtl);

    float* h1 = out;                       // [N,128]
    float* h2 = out + (size_t)N * 128;     // [N,128]
    float* h3 = out + (size_t)N * 256;     // [N,64]
    float* h4 = out + (size_t)N * 320;     // [N,32]

    // Opt in to >48KB dynamic smem for each GEMM instantiation (idempotent,
    // capture-legal host API — no stream ops, no allocation).
    cudaFuncSetAttribute(gemm_tc<256, 128, -1>,
                         cudaFuncAttributeMaxDynamicSharedMemorySize, GemmSmem<128>::BYTES);
    cudaFuncSetAttribute(gemm_tc<128, 128, 0>,
                         cudaFuncAttributeMaxDynamicSharedMemorySize, GemmSmem<128>::BYTES);
    cudaFuncSetAttribute(gemm_tc<128, 64, 1>,
                         cudaFuncAttributeMaxDynamicSharedMemorySize, GemmSmem<64>::BYTES);
    cudaFuncSetAttribute(gemm_tc<64, 32, 2>,
                         cudaFuncAttributeMaxDynamicSharedMemorySize, GemmSmem<32>::BYTES);

    zero_stats_kernel<<<1, 128>>>();
    rowptr_kernel<<<(N + 256) / 256, 256>>>(adj_row, N, E);
    wsplit_all_kernel<<<(59392 + 255) / 256, 256>>>(W1, W2, W3, W4);

    const int gemm_blocks = (N + 127) / 128;
    const int spmm_blocks = (N + 7) / 8;
    const int norm_blocks = 1184;  // 8 * 148

    // Layer 1: support = x @ W1 ; t1 = act(spmm)
    gemm_tc<256, 128, -1><<<gemm_blocks, 256, GemmSmem<128>::BYTES>>>(
        x, wth + 0, wtl + 0, g_support_p, nullptr, N);
    spmm_kernel<128, 0><<<spmm_blocks, 256>>>(g_support_p, adj_col, adj_vals, g_t_p, N);

    // Layer 2: GEMM reads t1, fuses BN(layer0): writes h1 AND support = h1 @ W2
    gemm_tc<128, 128, 0><<<gemm_blocks, 256, GemmSmem<128>::BYTES>>>(
        g_t_p, wth + 32768, wtl + 32768, g_support_p, h1, N);
    spmm_kernel<128, 1><<<spmm_blocks, 256>>>(g_support_p, adj_col, adj_vals, g_t_p, N);

    // Layer 3: GEMM reads t2, fuses BN(layer1): writes h2 AND support = h2 @ W3
    gemm_tc<128, 64, 1><<<gemm_blocks, 256, GemmSmem<64>::BYTES>>>(
        g_t_p, wth + 49152, wtl + 49152, g_support_p, h2, N);
    spmm_kernel<64, 2><<<spmm_blocks, 256>>>(g_support_p, adj_col, adj_vals, g_t_p, N);

    // Layer 4: GEMM reads t3, fuses BN(layer2): writes h3 AND support = h3 @ W4
    gemm_tc<64, 32, 2><<<gemm_blocks, 256, GemmSmem<32>::BYTES>>>(
        g_t_p, wth + 57344, wtl + 57344, g_support_p, h3, N);
    spmm_kernel<32, 3><<<spmm_blocks, 256>>>(g_support_p, adj_col, adj_vals, g_t_p, N);

    // Final norm for h4
    norm_kernel<32, 3><<<norm_blocks, 256>>>(g_t_p, h4, N);
}

// round 14
// speedup vs baseline: 1.0096x; 1.0096x over previous
#include <cuda_runtime.h>
#include <cuda_fp16.h>
#include <cuda_bf16.h>
#include <math.h>
#include <stdint.h>

#define NMAX 100000
#define EMAX 1600000

// Scratch (allocation-free rule: __device__ globals)
__device__ __half g_support[(size_t)NMAX * 128];
__device__ float  g_t[(size_t)NMAX * 128];
__device__ float  g_sum[4][128];
__device__ float  g_sq[4][128];
__device__ int    g_rowptr[NMAX + 1];
// Pre-split, pre-transposed weights: Wt[n][k] bf16 hi/lo planes.
// Offsets: W1t 0 (128x256), W2t 32768 (128x128), W3t 49152 (64x128), W4t 57344 (32x64)
__device__ __nv_bfloat16 g_wth[61440];
__device__ __nv_bfloat16 g_wtl[61440];

// ---------------------------------------------------------------------------
__global__ void zero_stats_kernel() {
    int i = threadIdx.x;
    if (i < 128) {
        #pragma unroll
        for (int l = 0; l < 4; l++) { g_sum[l][i] = 0.f; g_sq[l][i] = 0.f; }
    }
}

// ---------------------------------------------------------------------------
// CSR row_ptr from sorted adj_row via binary search (lower_bound of r).
__global__ void rowptr_kernel(const int* __restrict__ adj_row, int N, int E) {
    int r = blockIdx.x * blockDim.x + threadIdx.x;
    if (r > N) return;
    int lo = 0, hi = E;
    while (lo < hi) {
        int mid = (lo + hi) >> 1;
        if (adj_row[mid] < r) lo = mid + 1; else hi = mid;
    }
    g_rowptr[r] = lo;
}

// ---------------------------------------------------------------------------
// Split ALL FOUR W[k][n] into bf16 hi/lo, transposed to Wt[n][k]. One launch.
__global__ void wsplit_all_kernel(const float* __restrict__ W1,
                                  const float* __restrict__ W2,
                                  const float* __restrict__ W3,
                                  const float* __restrict__ W4) {
    int gidx = blockIdx.x * blockDim.x + threadIdx.x;
    const float* W; int K, OUT, base, idx;
    if (gidx < 32768)       { W = W1; K = 256; OUT = 128; base = 0;     idx = gidx; }
    else if (gidx < 49152)  { W = W2; K = 128; OUT = 128; base = 32768; idx = gidx - 32768; }
    else if (gidx < 57344)  { W = W3; K = 128; OUT = 64;  base = 49152; idx = gidx - 49152; }
    else if (gidx < 59392)  { W = W4; K = 64;  OUT = 32;  base = 57344; idx = gidx - 57344; }
    else return;
    int k = idx / OUT, n = idx % OUT;      // coalesced read
    float v = W[idx];
    __nv_bfloat16 h = __float2bfloat16_rn(v);
    float l = v - __bfloat162float(h);
    g_wth[base + (size_t)n * K + k] = h;
    g_wtl[base + (size_t)n * K + k] = __float2bfloat16_rn(l);
}

// ---------------------------------------------------------------------------
__device__ __forceinline__ void mma_bf16(float c[4], const uint32_t a[4],
                                         uint32_t b0, uint32_t b1) {
    asm volatile(
        "mma.sync.aligned.m16n8k16.row.col.f32.bf16.bf16.f32 "
        "{%0,%1,%2,%3}, {%4,%5,%6,%7}, {%8,%9}, {%0,%1,%2,%3};\n"
        : "+f"(c[0]), "+f"(c[1]), "+f"(c[2]), "+f"(c[3])
        : "r"(a[0]), "r"(a[1]), "r"(a[2]), "r"(a[3]), "r"(b0), "r"(b1));
}
__device__ __forceinline__ uint32_t pack_bf2(__nv_bfloat16 lo, __nv_bfloat16 hi) {
    __nv_bfloat162 p; p.x = lo; p.y = hi;           // .x = lower 16 bits = lower k
    return *reinterpret_cast<uint32_t*>(&p);
}
__device__ __forceinline__ uint32_t smem_u32(const void* p) {
    return (uint32_t)__cvta_generic_to_shared(p);
}
__device__ __forceinline__ void ldsm_x4(uint32_t& r0, uint32_t& r1,
                                        uint32_t& r2, uint32_t& r3, uint32_t addr) {
    asm volatile("ldmatrix.sync.aligned.m8n8.x4.shared.b16 {%0,%1,%2,%3}, [%4];"
                 : "=r"(r0), "=r"(r1), "=r"(r2), "=r"(r3) : "r"(addr));
}
// Packed fp32x2 helpers (FFMA2 pipe — only reachable via PTX fma.rn.f32x2)
__device__ __forceinline__ uint64_t pack_f2(float x, float y) {
    uint64_t r;
    asm("mov.b64 %0, {%1, %2};" : "=l"(r) : "f"(x), "f"(y));
    return r;
}
__device__ __forceinline__ float2 unpack_f2(uint64_t v) {
    float2 f;
    asm("mov.b64 {%0, %1}, %2;" : "=f"(f.x), "=f"(f.y) : "l"(v));
    return f;
}
__device__ __forceinline__ void ffma2(uint64_t& d, uint64_t a, uint64_t b) {
    asm("fma.rn.f32x2 %0, %1, %2, %0;" : "+l"(d) : "l"(a), "l"(b));
}

// ---------------------------------------------------------------------------
// Tensor-core bf16x3 GEMM (hi*hi + hi*lo + lo*hi), fused input-BatchNorm.
// R12-exact configuration (measured best): static single-buffer smem,
// __launch_bounds__(256,2) -> regs 128 -> 2 CTA/SM; W direct load->STS.
// C[N,OUT] (fp16) = norm(A)[N,K] @ W[K,OUT]. BM=128, BK=32, 8 warps.
template<int K, int OUT, int LAYER>
__global__ __launch_bounds__(256, 2)
void gemm_tc(const float* __restrict__ A,
             const __nv_bfloat16* __restrict__ wth,
             const __nv_bfloat16* __restrict__ wtl,
             __half* __restrict__ C, float* __restrict__ Hout, int N) {
    constexpr int BM = 128, BK = 32;
    constexpr int SW = 20;     // A stride (words). LDSM rows 80B apart: distinct 16B banks mod 128
    constexpr int SWW = 36;    // W stride (words). 144B ≡ 16 mod 128: distinct
    constexpr int WARPS_M = (OUT >= 64) ? 4 : 8;
    constexpr int WARPS_N = 8 / WARPS_M;
    constexpr int WM = BM / WARPS_M;       // 32 or 16
    constexpr int WN = OUT / WARPS_N;      // 64 / 32 / 32
    constexpr int MT = WM / 16;            // 2 or 1
    constexpr int NT = WN / 8;             // 8 / 4 / 4
    constexpr int NA = (BM * BK) / (4 * 256);        // float4 A loads/thread = 4
    constexpr int WCHUNK = OUT * (BK / 8);           // uint4 (8 bf16) chunks per W tile

    __shared__ uint32_t Ah32[BM][SW], Al32[BM][SW];
    __shared__ uint32_t Wc32[OUT][SWW];
    __shared__ float mean_s[128], r_s[128];

    const int tid = threadIdx.x;
    const int w = tid >> 5, lane = tid & 31;
    const int wm = (WARPS_N == 2) ? (w >> 1) : w;
    const int wn = (WARPS_N == 2) ? (w & 1) : 0;
    const int row0 = blockIdx.x * BM;
    const int li = lane & 7, lsel = lane >> 3;     // LDSM address lanes

    if (LAYER >= 0) {
        const float invN = 1.f / (float)N;
        for (int i = tid; i < K; i += 256) {
            float m = g_sum[LAYER][i] * invN;
            float var = g_sq[LAYER][i] * invN - m * m;
            mean_s[i] = m;
            r_s[i] = rsqrtf(var + 1e-5f);
        }
        __syncthreads();
    }

    float acc[MT][NT][4];
    #pragma unroll
    for (int mt = 0; mt < MT; mt++)
        #pragma unroll
        for (int nt = 0; nt < NT; nt++)
            #pragma unroll
            for (int q = 0; q < 4; q++) acc[mt][nt][q] = 0.f;

    float4 stA[NA];   // A register staging only (W has no staging regs)

    auto load_tile = [&](int kb) {
        #pragma unroll
        for (int p = 0; p < NA; p++) {
            int idx = p * 256 + tid;
            int r = idx >> 3;                  // BK/4 = 8 float4 per row
            int kq = (idx & 7) * 4;
            int gr = row0 + r;
            float4 v = make_float4(0.f, 0.f, 0.f, 0.f);
            if (gr < N) {
                v = *(const float4*)(A + (size_t)gr * K + kb + kq);
                if (LAYER >= 0) {
                    int c = kb + kq;
                    v.x = (v.x - mean_s[c + 0]) * r_s[c + 0];
                    v.y = (v.y - mean_s[c + 1]) * r_s[c + 1];
                    v.z = (v.z - mean_s[c + 2]) * r_s[c + 2];
                    v.w = (v.w - mean_s[c + 3]) * r_s[c + 3];
                    *(float4*)(Hout + (size_t)gr * K + c) = v;
                }
            }
            stA[p] = v;
        }
    };
    auto store_tile = [&](int kb) {
        #pragma unroll
        for (int p = 0; p < NA; p++) {
            int idx = p * 256 + tid;
            int r = idx >> 3;
            int kq = (idx & 7) * 4;
            float4 v = stA[p];
            __nv_bfloat16 hx = __float2bfloat16_rn(v.x);
            __nv_bfloat16 hy = __float2bfloat16_rn(v.y);
            __nv_bfloat16 hz = __float2bfloat16_rn(v.z);
            __nv_bfloat16 hw = __float2bfloat16_rn(v.w);
            uint2 hh = make_uint2(pack_bf2(hx, hy), pack_bf2(hz, hw));
            uint2 ll = make_uint2(
                pack_bf2(__float2bfloat16_rn(v.x - __bfloat162float(hx)),
                         __float2bfloat16_rn(v.y - __bfloat162float(hy))),
                pack_bf2(__float2bfloat16_rn(v.z - __bfloat162float(hz)),
                         __float2bfloat16_rn(v.w - __bfloat162float(hw))));
            *(uint2*)&Ah32[r][kq >> 1] = hh;
            *(uint2*)&Al32[r][kq >> 1] = ll;
        }
        // W: direct load -> STS (no staging regs; L2-resident, latency hidden
        // by the co-resident CTA)
        #pragma unroll
        for (int p = 0; p < (WCHUNK + 255) / 256; p++) {
            int idx = p * 256 + tid;
            if ((WCHUNK % 256 == 0) || idx < WCHUNK) {
                int n = idx >> 2, part = idx & 3;
                uint4 hv = *(const uint4*)(wth + (size_t)n * K + kb + part * 8);
                uint4 lv = *(const uint4*)(wtl + (size_t)n * K + kb + part * 8);
                int s = part >> 1, half = part & 1;      // k16 step, b0/b1 half
                *(uint4*)&Wc32[n][s * 16 + half * 4]     = hv;
                *(uint4*)&Wc32[n][s * 16 + 8 + half * 4] = lv;
            }
        }
    };

    load_tile(0);
    store_tile(0);
    __syncthreads();

    for (int kb = 0; kb < K; kb += BK) {
        const bool last = (kb + BK >= K);
        if (!last) load_tile(kb + BK);     // prefetch next A tile into registers

        #pragma unroll
        for (int s = 0; s < 2; s++) {                 // two k16 steps per BK=32 tile
            const int ks8 = s * 8;
            uint32_t ah[MT][4], al[MT][4];
            #pragma unroll
            for (int mt = 0; mt < MT; mt++) {
                int mrow = wm * WM + mt * 16 + (lsel & 1) * 8 + li;
                uint32_t acol = ks8 + (lsel >> 1) * 4;
                ldsm_x4(ah[mt][0], ah[mt][1], ah[mt][2], ah[mt][3],
                        smem_u32(&Ah32[mrow][acol]));
                ldsm_x4(al[mt][0], al[mt][1], al[mt][2], al[mt][3],
                        smem_u32(&Al32[mrow][acol]));
            }
            #pragma unroll
            for (int nt = 0; nt < NT; nt++) {
                int n = wn * WN + nt * 8 + li;
                uint32_t bh0, bh1, bl0, bl1;
                ldsm_x4(bh0, bh1, bl0, bl1,
                        smem_u32(&Wc32[n][s * 16 + lsel * 4]));
                #pragma unroll
                for (int mt = 0; mt < MT; mt++) {
                    mma_bf16(acc[mt][nt], ah[mt], bh0, bh1);  // hi*hi
                    mma_bf16(acc[mt][nt], ah[mt], bl0, bl1);  // hi*lo
                    mma_bf16(acc[mt][nt], al[mt], bh0, bh1);  // lo*hi
                }
            }
        }
        if (!last) {
            __syncthreads();
            store_tile(kb + BK);
            __syncthreads();
        }
    }

    // Epilogue -> fp16 support. c0,c1 at (row, t*2); c2,c3 at (row+8, t*2).
    const int g = lane >> 2, t = lane & 3;
    #pragma unroll
    for (int mt = 0; mt < MT; mt++) {
        int r0 = row0 + wm * WM + mt * 16 + g;
        #pragma unroll
        for (int nt = 0; nt < NT; nt++) {
            int n = wn * WN + nt * 8 + t * 2;
            if (r0 < N)
                *(__half2*)(C + (size_t)r0 * OUT + n) =
                    __floats2half2_rn(acc[mt][nt][0], acc[mt][nt][1]);
            if (r0 + 8 < N)
                *(__half2*)(C + (size_t)(r0 + 8) * OUT + n) =
                    __floats2half2_rn(acc[mt][nt][2], acc[mt][nt][3]);
        }
    }
}

// ---------------------------------------------------------------------------
// SpMM (warp per row, CSR) over fp16 support + leaky_relu + elu fused.
// R14: packed fp32x2 accumulation via fma.rn.f32x2 (FFMA2) — halves the
// FMA instruction count per edge (spmm is issue-bound: fma 34% + alu 30%).
// half2 coalesced gathers, 4-edge unroll, scalar metadata loads (measured
// best). Numerically identical to scalar fp32 (same lattice ops, paired).
template<int OUT, int LAYER>
__global__ __launch_bounds__(256)
void spmm_kernel(const __half* __restrict__ support,
                 const int* __restrict__ col,
                 const float* __restrict__ vals,
                 float* __restrict__ t, int N) {
    constexpr int H2 = (OUT >= 64) ? OUT / 64 : 0;   // half2 loads/lane: 2,1,0
    __shared__ float ssum[OUT], ssq[OUT];
    const int tid = threadIdx.x;
    for (int i = tid; i < OUT; i += blockDim.x) { ssum[i] = 0.f; ssq[i] = 0.f; }
    __syncthreads();

    const int lane = tid & 31;
    const int warp = tid >> 5;
    const int row = blockIdx.x * 8 + warp;

    if (row < N) {
        const int s = g_rowptr[row];
        const int e = g_rowptr[row + 1];

        if constexpr (H2 >= 1) {
            uint64_t acc2[H2];
            #pragma unroll
            for (int h = 0; h < H2; h++) acc2[h] = pack_f2(0.f, 0.f);

            int i = s;
            for (; i + 4 <= e; i += 4) {
                int c0 = __ldg(&col[i]),     c1 = __ldg(&col[i + 1]);
                int c2 = __ldg(&col[i + 2]), c3 = __ldg(&col[i + 3]);
                float v0 = __ldg(&vals[i]),     v1 = __ldg(&vals[i + 1]);
                float v2 = __ldg(&vals[i + 2]), v3 = __ldg(&vals[i + 3]);
                const __half2* p0 = (const __half2*)(support + (size_t)c0 * OUT) + lane;
                const __half2* p1 = (const __half2*)(support + (size_t)c1 * OUT) + lane;
                const __half2* p2 = (const __half2*)(support + (size_t)c2 * OUT) + lane;
                const __half2* p3 = (const __half2*)(support + (size_t)c3 * OUT) + lane;
                __half2 m0[H2], m1[H2], m2[H2], m3[H2];
                #pragma unroll
                for (int h = 0; h < H2; h++) m0[h] = __ldg(p0 + h * 32);
                #pragma unroll
                for (int h = 0; h < H2; h++) m1[h] = __ldg(p1 + h * 32);
                #pragma unroll
                for (int h = 0; h < H2; h++) m2[h] = __ldg(p2 + h * 32);
                #pragma unroll
                for (int h = 0; h < H2; h++) m3[h] = __ldg(p3 + h * 32);
                uint64_t vv0 = pack_f2(v0, v0), vv1 = pack_f2(v1, v1);
                uint64_t vv2 = pack_f2(v2, v2), vv3 = pack_f2(v3, v3);
                #pragma unroll
                for (int h = 0; h < H2; h++) {
                    float2 f0 = __half22float2(m0[h]);
                    float2 f1 = __half22float2(m1[h]);
                    float2 f2 = __half22float2(m2[h]);
                    float2 f3 = __half22float2(m3[h]);
                    ffma2(acc2[h], vv0, pack_f2(f0.x, f0.y));
                    ffma2(acc2[h], vv1, pack_f2(f1.x, f1.y));
                    ffma2(acc2[h], vv2, pack_f2(f2.x, f2.y));
                    ffma2(acc2[h], vv3, pack_f2(f3.x, f3.y));
                }
            }
            for (; i < e; i++) {
                int c = __ldg(&col[i]);
                float v = __ldg(&vals[i]);
                const __half2* p = (const __half2*)(support + (size_t)c * OUT) + lane;
                uint64_t vv = pack_f2(v, v);
                #pragma unroll
                for (int h = 0; h < H2; h++) {
                    float2 f = __half22float2(__ldg(p + h * 32));
                    ffma2(acc2[h], vv, pack_f2(f.x, f.y));
                }
            }

            // leaky_relu(0.2) then elu; sign preserved -> single branch
            float* trow = t + (size_t)row * OUT;
            #pragma unroll
            for (int h = 0; h < H2; h++) {
                float2 a = unpack_f2(acc2[h]);
                float tx = (a.x > 0.f) ? a.x : expm1f(0.2f * a.x);
                float ty = (a.y > 0.f) ? a.y : expm1f(0.2f * a.y);
                int c = 64 * h + 2 * lane;
                *(float2*)(trow + c) = make_float2(tx, ty);
                atomicAdd(&ssum[c + 0], tx);
                atomicAdd(&ssum[c + 1], ty);
                atomicAdd(&ssq[c + 0], tx * tx);
                atomicAdd(&ssq[c + 1], ty * ty);
            }
        } else {
            float acc = 0.f;
            int i = s;
            for (; i + 4 <= e; i += 4) {
                int c0 = __ldg(&col[i]),     c1 = __ldg(&col[i + 1]);
                int c2 = __ldg(&col[i + 2]), c3 = __ldg(&col[i + 3]);
                float v0 = __ldg(&vals[i]),     v1 = __ldg(&vals[i + 1]);
                float v2 = __ldg(&vals[i + 2]), v3 = __ldg(&vals[i + 3]);
                float f0 = __half2float(__ldg(support + (size_t)c0 * OUT + lane));
                float f1 = __half2float(__ldg(support + (size_t)c1 * OUT + lane));
                float f2 = __half2float(__ldg(support + (size_t)c2 * OUT + lane));
                float f3 = __half2float(__ldg(support + (size_t)c3 * OUT + lane));
                acc = fmaf(v3, f3, fmaf(v2, f2, fmaf(v1, f1, fmaf(v0, f0, acc))));
            }
            for (; i < e; i++) {
                int c = __ldg(&col[i]);
                float v = __ldg(&vals[i]);
                acc = fmaf(v, __half2float(__ldg(support + (size_t)c * OUT + lane)), acc);
            }
            float tv = (acc > 0.f) ? acc : expm1f(0.2f * acc);
            t[(size_t)row * OUT + lane] = tv;
            atomicAdd(&ssum[lane], tv);
            atomicAdd(&ssq[lane], tv * tv);
        }
    }
    __syncthreads();
    for (int i = tid; i < OUT; i += blockDim.x) {
        atomicAdd(&g_sum[LAYER][i], ssum[i]);
        atomicAdd(&g_sq[LAYER][i], ssq[i]);
    }
}

// ---------------------------------------------------------------------------
// BatchNorm (final layer only): out = (t - mean) * rsqrt(var + eps)
template<int OUT, int LAYER>
__global__ void norm_kernel(const float* __restrict__ t, float* __restrict__ out, int N) {
    __shared__ float mean_s[OUT], r_s[OUT];
    const float invN = 1.f / (float)N;
    for (int i = threadIdx.x; i < OUT; i += blockDim.x) {
        float m = g_sum[LAYER][i] * invN;
        float var = g_sq[LAYER][i] * invN - m * m;
        mean_s[i] = m;
        r_s[i] = rsqrtf(var + 1e-5f);
    }
    __syncthreads();
    const float4* t4 = (const float4*)t;
    float4* o4 = (float4*)out;
    size_t total4 = (size_t)N * OUT / 4;
    for (size_t i = (size_t)blockIdx.x * blockDim.x + threadIdx.x; i < total4;
         i += (size_t)gridDim.x * blockDim.x) {
        int cb = (int)(i & (OUT / 4 - 1)) * 4;
        float4 v = t4[i];
        float4 r;
        r.x = (v.x - mean_s[cb + 0]) * r_s[cb + 0];
        r.y = (v.y - mean_s[cb + 1]) * r_s[cb + 1];
        r.z = (v.z - mean_s[cb + 2]) * r_s[cb + 2];
        r.w = (v.w - mean_s[cb + 3]) * r_s[cb + 3];
        o4[i] = r;
    }
}

// ---------------------------------------------------------------------------
extern "C" void kernel_launch(void* const* d_in, const int* in_sizes, int n_in,
                              void* d_out, int out_size) {
    const float* x        = (const float*)d_in[0];
    const int*   adj_row  = (const int*)d_in[1];
    const int*   adj_col  = (const int*)d_in[2];
    const float* adj_vals = (const float*)d_in[3];
    const float* W1 = (const float*)d_in[4];
    const float* W2 = (const float*)d_in[5];
    const float* W3 = (const float*)d_in[6];
    const float* W4 = (const float*)d_in[7];
    float* out = (float*)d_out;

    const int N = in_sizes[0] / 256;
    const int E = in_sizes[1];

    __half* g_support_p; cudaGetSymbolAddress((void**)&g_support_p, g_support);
    float*  g_t_p;       cudaGetSymbolAddress((void**)&g_t_p, g_t);
    __nv_bfloat16* wth;  cudaGetSymbolAddress((void**)&wth, g_wth);
    __nv_bfloat16* wtl;  cudaGetSymbolAddress((void**)&wtl, g_wtl);

    float* h1 = out;                       // [N,128]
    float* h2 = out + (size_t)N * 128;     // [N,128]
    float* h3 = out + (size_t)N * 256;     // [N,64]
    float* h4 = out + (size_t)N * 320;     // [N,32]

    zero_stats_kernel<<<1, 128>>>();
    rowptr_kernel<<<(N + 256) / 256, 256>>>(adj_row, N, E);
    wsplit_all_kernel<<<(59392 + 255) / 256, 256>>>(W1, W2, W3, W4);

    const int gemm_blocks = (N + 127) / 128;
    const int spmm_blocks = (N + 7) / 8;
    const int norm_blocks = 1184;  // 8 * 148

    // Layer 1: support = x @ W1 ; t1 = act(spmm)
    gemm_tc<256, 128, -1><<<gemm_blocks, 256>>>(x, wth + 0, wtl + 0, g_support_p, nullptr, N);
    spmm_kernel<128, 0><<<spmm_blocks, 256>>>(g_support_p, adj_col, adj_vals, g_t_p, N);

    // Layer 2: GEMM reads t1, fuses BN(layer0): writes h1 AND support = h1 @ W2
    gemm_tc<128, 128, 0><<<gemm_blocks, 256>>>(g_t_p, wth + 32768, wtl + 32768, g_support_p, h1, N);
    spmm_kernel<128, 1><<<spmm_blocks, 256>>>(g_support_p, adj_col, adj_vals, g_t_p, N);

    // Layer 3: GEMM reads t2, fuses BN(layer1): writes h2 AND support = h2 @ W3
    gemm_tc<128, 64, 1><<<gemm_blocks, 256>>>(g_t_p, wth + 49152, wtl + 49152, g_support_p, h2, N);
    spmm_kernel<64, 2><<<spmm_blocks, 256>>>(g_support_p, adj_col, adj_vals, g_t_p, N);

    // Layer 4: GEMM reads t3, fuses BN(layer2): writes h3 AND support = h3 @ W4
    gemm_tc<64, 32, 2><<<gemm_blocks, 256>>>(g_t_p, wth + 57344, wtl + 57344, g_support_p, h3, N);
    spmm_kernel<32, 3><<<spmm_blocks, 256>>>(g_support_p, adj_col, adj_vals, g_t_p, N);

    // Final norm for h4
    norm_kernel<32, 3><<<norm_blocks, 256>>>(g_t_p, h4, N);
}

// round 15
// speedup vs baseline: 1.0311x; 1.0213x over previous
#include <cuda_runtime.h>
#include <cuda_fp16.h>
#include <cuda_bf16.h>
#include <math.h>
#include <stdint.h>

#define NMAX 100000
#define EMAX 1600000

// Scratch (allocation-free rule: __device__ globals)
__device__ __half g_support[(size_t)NMAX * 128];
__device__ float  g_t[(size_t)NMAX * 128];
__device__ float  g_sum[4][128];
__device__ float  g_sq[4][128];
__device__ int    g_rowptr[NMAX + 1];
// Pre-split, pre-transposed weights: Wt[n][k] bf16 hi/lo planes.
// Offsets: W1t 0 (128x256), W2t 32768 (128x128), W3t 49152 (64x128), W4t 57344 (32x64)
__device__ __nv_bfloat16 g_wth[61440];
__device__ __nv_bfloat16 g_wtl[61440];

// ---------------------------------------------------------------------------
// ONE fused setup kernel: zero stats + CSR rowptr (binary search over sorted
// adj_row) + W split/transpose into bf16 hi/lo planes.
__global__ void setup_kernel(const int* __restrict__ adj_row, int N, int E,
                             const float* __restrict__ W1,
                             const float* __restrict__ W2,
                             const float* __restrict__ W3,
                             const float* __restrict__ W4) {
    int gidx = blockIdx.x * blockDim.x + threadIdx.x;

    if (gidx < 128) {
        #pragma unroll
        for (int l = 0; l < 4; l++) { g_sum[l][gidx] = 0.f; g_sq[l][gidx] = 0.f; }
    }

    if (gidx <= N) {
        int lo = 0, hi = E;
        while (lo < hi) {
            int mid = (lo + hi) >> 1;
            if (adj_row[mid] < gidx) lo = mid + 1; else hi = mid;
        }
        g_rowptr[gidx] = lo;
    }

    if (gidx < 59392) {
        const float* W; int K, OUT, base, idx;
        if (gidx < 32768)       { W = W1; K = 256; OUT = 128; base = 0;     idx = gidx; }
        else if (gidx < 49152)  { W = W2; K = 128; OUT = 128; base = 32768; idx = gidx - 32768; }
        else if (gidx < 57344)  { W = W3; K = 128; OUT = 64;  base = 49152; idx = gidx - 49152; }
        else                    { W = W4; K = 64;  OUT = 32;  base = 57344; idx = gidx - 57344; }
        int k = idx / OUT, n = idx % OUT;      // coalesced read
        float v = W[idx];
        __nv_bfloat16 h = __float2bfloat16_rn(v);
        float l = v - __bfloat162float(h);
        g_wth[base + (size_t)n * K + k] = h;
        g_wtl[base + (size_t)n * K + k] = __float2bfloat16_rn(l);
    }
}

// ---------------------------------------------------------------------------
__device__ __forceinline__ void mma_bf16(float c[4], const uint32_t a[4],
                                         uint32_t b0, uint32_t b1) {
    asm volatile(
        "mma.sync.aligned.m16n8k16.row.col.f32.bf16.bf16.f32 "
        "{%0,%1,%2,%3}, {%4,%5,%6,%7}, {%8,%9}, {%0,%1,%2,%3};\n"
        : "+f"(c[0]), "+f"(c[1]), "+f"(c[2]), "+f"(c[3])
        : "r"(a[0]), "r"(a[1]), "r"(a[2]), "r"(a[3]), "r"(b0), "r"(b1));
}
__device__ __forceinline__ uint32_t pack_bf2(__nv_bfloat16 lo, __nv_bfloat16 hi) {
    __nv_bfloat162 p; p.x = lo; p.y = hi;           // .x = lower 16 bits = lower k
    return *reinterpret_cast<uint32_t*>(&p);
}
__device__ __forceinline__ uint32_t smem_u32(const void* p) {
    return (uint32_t)__cvta_generic_to_shared(p);
}
__device__ __forceinline__ void ldsm_x4(uint32_t& r0, uint32_t& r1,
                                        uint32_t& r2, uint32_t& r3, uint32_t addr) {
    asm volatile("ldmatrix.sync.aligned.m8n8.x4.shared.b16 {%0,%1,%2,%3}, [%4];"
                 : "=r"(r0), "=r"(r1), "=r"(r2), "=r"(r3) : "r"(addr));
}

// ---------------------------------------------------------------------------
// Tensor-core bf16x3 GEMM (hi*hi + hi*lo + lo*hi), fused input-BatchNorm.
// R12-exact configuration (measured best): static single-buffer smem,
// __launch_bounds__(256,2) -> regs 128 -> 2 CTA/SM; W direct load->STS.
// C[N,OUT] (fp16) = norm(A)[N,K] @ W[K,OUT]. BM=128, BK=32, 8 warps.
template<int K, int OUT, int LAYER>
__global__ __launch_bounds__(256, 2)
void gemm_tc(const float* __restrict__ A,
             const __nv_bfloat16* __restrict__ wth,
             const __nv_bfloat16* __restrict__ wtl,
             __half* __restrict__ C, float* __restrict__ Hout, int N) {
    constexpr int BM = 128, BK = 32;
    constexpr int SW = 20;     // A stride (words). LDSM rows 80B apart: distinct 16B banks mod 128
    constexpr int SWW = 36;    // W stride (words). 144B ≡ 16 mod 128: distinct
    constexpr int WARPS_M = (OUT >= 64) ? 4 : 8;
    constexpr int WARPS_N = 8 / WARPS_M;
    constexpr int WM = BM / WARPS_M;       // 32 or 16
    constexpr int WN = OUT / WARPS_N;      // 64 / 32 / 32
    constexpr int MT = WM / 16;            // 2 or 1
    constexpr int NT = WN / 8;             // 8 / 4 / 4
    constexpr int NA = (BM * BK) / (4 * 256);        // float4 A loads/thread = 4
    constexpr int WCHUNK = OUT * (BK / 8);           // uint4 (8 bf16) chunks per W tile

    __shared__ uint32_t Ah32[BM][SW], Al32[BM][SW];
    __shared__ uint32_t Wc32[OUT][SWW];
    __shared__ float mean_s[128], r_s[128];

    const int tid = threadIdx.x;
    const int w = tid >> 5, lane = tid & 31;
    const int wm = (WARPS_N == 2) ? (w >> 1) : w;
    const int wn = (WARPS_N == 2) ? (w & 1) : 0;
    const int row0 = blockIdx.x * BM;
    const int li = lane & 7, lsel = lane >> 3;     // LDSM address lanes

    if (LAYER >= 0) {
        const float invN = 1.f / (float)N;
        for (int i = tid; i < K; i += 256) {
            float m = g_sum[LAYER][i] * invN;
            float var = g_sq[LAYER][i] * invN - m * m;
            mean_s[i] = m;
            r_s[i] = rsqrtf(var + 1e-5f);
        }
        __syncthreads();
    }

    float acc[MT][NT][4];
    #pragma unroll
    for (int mt = 0; mt < MT; mt++)
        #pragma unroll
        for (int nt = 0; nt < NT; nt++)
            #pragma unroll
            for (int q = 0; q < 4; q++) acc[mt][nt][q] = 0.f;

    float4 stA[NA];   // A register staging only (W has no staging regs)

    auto load_tile = [&](int kb) {
        #pragma unroll
        for (int p = 0; p < NA; p++) {
            int idx = p * 256 + tid;
            int r = idx >> 3;                  // BK/4 = 8 float4 per row
            int kq = (idx & 7) * 4;
            int gr = row0 + r;
            float4 v = make_float4(0.f, 0.f, 0.f, 0.f);
            if (gr < N) {
                v = *(const float4*)(A + (size_t)gr * K + kb + kq);
                if (LAYER >= 0) {
                    int c = kb + kq;
                    v.x = (v.x - mean_s[c + 0]) * r_s[c + 0];
                    v.y = (v.y - mean_s[c + 1]) * r_s[c + 1];
                    v.z = (v.z - mean_s[c + 2]) * r_s[c + 2];
                    v.w = (v.w - mean_s[c + 3]) * r_s[c + 3];
                    *(float4*)(Hout + (size_t)gr * K + c) = v;
                }
            }
            stA[p] = v;
        }
    };
    auto store_tile = [&](int kb) {
        #pragma unroll
        for (int p = 0; p < NA; p++) {
            int idx = p * 256 + tid;
            int r = idx >> 3;
            int kq = (idx & 7) * 4;
            float4 v = stA[p];
            __nv_bfloat16 hx = __float2bfloat16_rn(v.x);
            __nv_bfloat16 hy = __float2bfloat16_rn(v.y);
            __nv_bfloat16 hz = __float2bfloat16_rn(v.z);
            __nv_bfloat16 hw = __float2bfloat16_rn(v.w);
            uint2 hh = make_uint2(pack_bf2(hx, hy), pack_bf2(hz, hw));
            uint2 ll = make_uint2(
                pack_bf2(__float2bfloat16_rn(v.x - __bfloat162float(hx)),
                         __float2bfloat16_rn(v.y - __bfloat162float(hy))),
                pack_bf2(__float2bfloat16_rn(v.z - __bfloat162float(hz)),
                         __float2bfloat16_rn(v.w - __bfloat162float(hw))));
            *(uint2*)&Ah32[r][kq >> 1] = hh;
            *(uint2*)&Al32[r][kq >> 1] = ll;
        }
        // W: direct load -> STS (no staging regs; L2-resident, latency hidden
        // by the co-resident CTA)
        #pragma unroll
        for (int p = 0; p < (WCHUNK + 255) / 256; p++) {
            int idx = p * 256 + tid;
            if ((WCHUNK % 256 == 0) || idx < WCHUNK) {
                int n = idx >> 2, part = idx & 3;
                uint4 hv = *(const uint4*)(wth + (size_t)n * K + kb + part * 8);
                uint4 lv = *(const uint4*)(wtl + (size_t)n * K + kb + part * 8);
                int s = part >> 1, half = part & 1;      // k16 step, b0/b1 half
                *(uint4*)&Wc32[n][s * 16 + half * 4]     = hv;
                *(uint4*)&Wc32[n][s * 16 + 8 + half * 4] = lv;
            }
        }
    };

    load_tile(0);
    store_tile(0);
    __syncthreads();

    for (int kb = 0; kb < K; kb += BK) {
        const bool last = (kb + BK >= K);
        if (!last) load_tile(kb + BK);     // prefetch next A tile into registers

        #pragma unroll
        for (int s = 0; s < 2; s++) {                 // two k16 steps per BK=32 tile
            const int ks8 = s * 8;
            uint32_t ah[MT][4], al[MT][4];
            #pragma unroll
            for (int mt = 0; mt < MT; mt++) {
                int mrow = wm * WM + mt * 16 + (lsel & 1) * 8 + li;
                uint32_t acol = ks8 + (lsel >> 1) * 4;
                ldsm_x4(ah[mt][0], ah[mt][1], ah[mt][2], ah[mt][3],
                        smem_u32(&Ah32[mrow][acol]));
                ldsm_x4(al[mt][0], al[mt][1], al[mt][2], al[mt][3],
                        smem_u32(&Al32[mrow][acol]));
            }
            #pragma unroll
            for (int nt = 0; nt < NT; nt++) {
                int n = wn * WN + nt * 8 + li;
                uint32_t bh0, bh1, bl0, bl1;
                ldsm_x4(bh0, bh1, bl0, bl1,
                        smem_u32(&Wc32[n][s * 16 + lsel * 4]));
                #pragma unroll
                for (int mt = 0; mt < MT; mt++) {
                    mma_bf16(acc[mt][nt], ah[mt], bh0, bh1);  // hi*hi
                    mma_bf16(acc[mt][nt], ah[mt], bl0, bl1);  // hi*lo
                    mma_bf16(acc[mt][nt], al[mt], bh0, bh1);  // lo*hi
                }
            }
        }
        if (!last) {
            __syncthreads();
            store_tile(kb + BK);
            __syncthreads();
        }
    }

    // Epilogue -> fp16 support. c0,c1 at (row, t*2); c2,c3 at (row+8, t*2).
    const int g = lane >> 2, t = lane & 3;
    #pragma unroll
    for (int mt = 0; mt < MT; mt++) {
        int r0 = row0 + wm * WM + mt * 16 + g;
        #pragma unroll
        for (int nt = 0; nt < NT; nt++) {
            int n = wn * WN + nt * 8 + t * 2;
            if (r0 < N)
                *(__half2*)(C + (size_t)r0 * OUT + n) =
                    __floats2half2_rn(acc[mt][nt][0], acc[mt][nt][1]);
            if (r0 + 8 < N)
                *(__half2*)(C + (size_t)(r0 + 8) * OUT + n) =
                    __floats2half2_rn(acc[mt][nt][2], acc[mt][nt][3]);
        }
    }
}

// ---------------------------------------------------------------------------
// SpMM (CSR) over fp16 support + leaky_relu + elu fused.
// R15: EIGHT consecutive rows per warp (sequentially). Row degrees are
// ~Poisson(16); warp-per-row makes CTA runtime the max of 8 Poisson draws
// (~1.6x mean) and finished warps idle until the CTA exits — the measured
// ~67% issue ceiling. Summing 8 rows per warp cuts the relative spread to
// ~1.13x (util ~89%). Inner body is the R8 measured-best scalar-fma form.
template<int OUT, int LAYER>
__global__ __launch_bounds__(256)
void spmm_kernel(const __half* __restrict__ support,
                 const int* __restrict__ col,
                 const float* __restrict__ vals,
                 float* __restrict__ t, int N) {
    constexpr int H2 = (OUT >= 64) ? OUT / 64 : 0;   // half2 loads/lane: 2,1,0
    constexpr int JF = (OUT >= 64) ? 2 * H2 : 1;     // fp32 outputs/lane: 4,2,1
    constexpr int ROWS = 8;                          // rows per warp
    __shared__ float ssum[OUT], ssq[OUT];
    const int tid = threadIdx.x;
    for (int i = tid; i < OUT; i += blockDim.x) { ssum[i] = 0.f; ssq[i] = 0.f; }
    __syncthreads();

    const int lane = tid & 31;
    const int warp = tid >> 5;
    const int row0 = (blockIdx.x * 8 + warp) * ROWS;

    for (int rr = 0; rr < ROWS; rr++) {
        const int row = row0 + rr;
        if (row >= N) break;

        float acc[JF];
        #pragma unroll
        for (int j = 0; j < JF; j++) acc[j] = 0.f;

        const int s = g_rowptr[row];
        const int e = g_rowptr[row + 1];

        auto gather1 = [&](int i) {
            int c = __ldg(&col[i]);
            float v = __ldg(&vals[i]);
            const __half* p = support + (size_t)c * OUT;
            if constexpr (H2 >= 1) {
                #pragma unroll
                for (int h = 0; h < H2; h++) {
                    __half2 m = __ldg((const __half2*)p + h * 32 + lane);
                    float2 f = __half22float2(m);
                    acc[2 * h + 0] = fmaf(v, f.x, acc[2 * h + 0]);
                    acc[2 * h + 1] = fmaf(v, f.y, acc[2 * h + 1]);
                }
            } else {
                acc[0] = fmaf(v, __half2float(__ldg(p + lane)), acc[0]);
            }
        };

        int i = s;
        for (; i + 4 <= e; i += 4) {
            int c0 = __ldg(&col[i]),     c1 = __ldg(&col[i + 1]);
            int c2 = __ldg(&col[i + 2]), c3 = __ldg(&col[i + 3]);
            float v0 = __ldg(&vals[i]),     v1 = __ldg(&vals[i + 1]);
            float v2 = __ldg(&vals[i + 2]), v3 = __ldg(&vals[i + 3]);
            const __half* p0 = support + (size_t)c0 * OUT;
            const __half* p1 = support + (size_t)c1 * OUT;
            const __half* p2 = support + (size_t)c2 * OUT;
            const __half* p3 = support + (size_t)c3 * OUT;
            if constexpr (H2 >= 1) {
                __half2 m0[H2], m1[H2], m2[H2], m3[H2];
                #pragma unroll
                for (int h = 0; h < H2; h++) m0[h] = __ldg((const __half2*)p0 + h * 32 + lane);
                #pragma unroll
                for (int h = 0; h < H2; h++) m1[h] = __ldg((const __half2*)p1 + h * 32 + lane);
                #pragma unroll
                for (int h = 0; h < H2; h++) m2[h] = __ldg((const __half2*)p2 + h * 32 + lane);
                #pragma unroll
                for (int h = 0; h < H2; h++) m3[h] = __ldg((const __half2*)p3 + h * 32 + lane);
                #pragma unroll
                for (int h = 0; h < H2; h++) {
                    float2 f0 = __half22float2(m0[h]);
                    float2 f1 = __half22float2(m1[h]);
                    float2 f2 = __half22float2(m2[h]);
                    float2 f3 = __half22float2(m3[h]);
                    acc[2*h+0] = fmaf(v3, f3.x, fmaf(v2, f2.x, fmaf(v1, f1.x, fmaf(v0, f0.x, acc[2*h+0]))));
                    acc[2*h+1] = fmaf(v3, f3.y, fmaf(v2, f2.y, fmaf(v1, f1.y, fmaf(v0, f0.y, acc[2*h+1]))));
                }
            } else {
                float f0 = __half2float(__ldg(p0 + lane));
                float f1 = __half2float(__ldg(p1 + lane));
                float f2 = __half2float(__ldg(p2 + lane));
                float f3 = __half2float(__ldg(p3 + lane));
                acc[0] = fmaf(v3, f3, fmaf(v2, f2, fmaf(v1, f1, fmaf(v0, f0, acc[0]))));
            }
        }
        for (; i < e; i++) gather1(i);

        // leaky_relu(0.2) then elu; sign preserved -> single branch
        float tv[JF];
        #pragma unroll
        for (int j = 0; j < JF; j++) {
            float a = acc[j];
            tv[j] = (a > 0.f) ? a : expm1f(0.2f * a);
        }

        float* trow = t + (size_t)row * OUT;
        if constexpr (H2 >= 1) {
            #pragma unroll
            for (int h = 0; h < H2; h++) {
                int c = 64 * h + 2 * lane;
                *(float2*)(trow + c) = make_float2(tv[2*h+0], tv[2*h+1]);
                atomicAdd(&ssum[c + 0], tv[2*h+0]);
                atomicAdd(&ssum[c + 1], tv[2*h+1]);
                atomicAdd(&ssq[c + 0], tv[2*h+0] * tv[2*h+0]);
                atomicAdd(&ssq[c + 1], tv[2*h+1] * tv[2*h+1]);
            }
        } else {
            trow[lane] = tv[0];
            atomicAdd(&ssum[lane], tv[0]);
            atomicAdd(&ssq[lane], tv[0] * tv[0]);
        }
    }
    __syncthreads();
    for (int i = tid; i < OUT; i += blockDim.x) {
        atomicAdd(&g_sum[LAYER][i], ssum[i]);
        atomicAdd(&g_sq[LAYER][i], ssq[i]);
    }
}

// ---------------------------------------------------------------------------
// BatchNorm (final layer only): out = (t - mean) * rsqrt(var + eps)
template<int OUT, int LAYER>
__global__ void norm_kernel(const float* __restrict__ t, float* __restrict__ out, int N) {
    __shared__ float mean_s[OUT], r_s[OUT];
    const float invN = 1.f / (float)N;
    for (int i = threadIdx.x; i < OUT; i += blockDim.x) {
        float m = g_sum[LAYER][i] * invN;
        float var = g_sq[LAYER][i] * invN - m * m;
        mean_s[i] = m;
        r_s[i] = rsqrtf(var + 1e-5f);
    }
    __syncthreads();
    const float4* t4 = (const float4*)t;
    float4* o4 = (float4*)out;
    size_t total4 = (size_t)N * OUT / 4;
    for (size_t i = (size_t)blockIdx.x * blockDim.x + threadIdx.x; i < total4;
         i += (size_t)gridDim.x * blockDim.x) {
        int cb = (int)(i & (OUT / 4 - 1)) * 4;
        float4 v = t4[i];
        float4 r;
        r.x = (v.x - mean_s[cb + 0]) * r_s[cb + 0];
        r.y = (v.y - mean_s[cb + 1]) * r_s[cb + 1];
        r.z = (v.z - mean_s[cb + 2]) * r_s[cb + 2];
        r.w = (v.w - mean_s[cb + 3]) * r_s[cb + 3];
        o4[i] = r;
    }
}

// ---------------------------------------------------------------------------
extern "C" void kernel_launch(void* const* d_in, const int* in_sizes, int n_in,
                              void* d_out, int out_size) {
    const float* x        = (const float*)d_in[0];
    const int*   adj_row  = (const int*)d_in[1];
    const int*   adj_col  = (const int*)d_in[2];
    const float* adj_vals = (const float*)d_in[3];
    const float* W1 = (const float*)d_in[4];
    const float* W2 = (const float*)d_in[5];
    const float* W3 = (const float*)d_in[6];
    const float* W4 = (const float*)d_in[7];
    float* out = (float*)d_out;

    const int N = in_sizes[0] / 256;
    const int E = in_sizes[1];

    __half* g_support_p; cudaGetSymbolAddress((void**)&g_support_p, g_support);
    float*  g_t_p;       cudaGetSymbolAddress((void**)&g_t_p, g_t);
    __nv_bfloat16* wth;  cudaGetSymbolAddress((void**)&wth, g_wth);
    __nv_bfloat16* wtl;  cudaGetSymbolAddress((void**)&wtl, g_wtl);

    float* h1 = out;                       // [N,128]
    float* h2 = out + (size_t)N * 128;     // [N,128]
    float* h3 = out + (size_t)N * 256;     // [N,64]
    float* h4 = out + (size_t)N * 320;     // [N,32]

    // One fused setup launch (stats zero + rowptr + W split)
    const int setup_threads = (N + 1 > 59392) ? N + 1 : 59392;
    setup_kernel<<<(setup_threads + 255) / 256, 256>>>(adj_row, N, E, W1, W2, W3, W4);

    const int gemm_blocks = (N + 127) / 128;
    const int spmm_blocks = (N + 63) / 64;     // 8 warps x 8 rows per CTA
    const int norm_blocks = 1184;  // 8 * 148

    // Layer 1: support = x @ W1 ; t1 = act(spmm)
    gemm_tc<256, 128, -1><<<gemm_blocks, 256>>>(x, wth + 0, wtl + 0, g_support_p, nullptr, N);
    spmm_kernel<128, 0><<<spmm_blocks, 256>>>(g_support_p, adj_col, adj_vals, g_t_p, N);

    // Layer 2: GEMM reads t1, fuses BN(layer0): writes h1 AND support = h1 @ W2
    gemm_tc<128, 128, 0><<<gemm_blocks, 256>>>(g_t_p, wth + 32768, wtl + 32768, g_support_p, h1, N);
    spmm_kernel<128, 1><<<spmm_blocks, 256>>>(g_support_p, adj_col, adj_vals, g_t_p, N);

    // Layer 3: GEMM reads t2, fuses BN(layer1): writes h2 AND support = h2 @ W3
    gemm_tc<128, 64, 1><<<gemm_blocks, 256>>>(g_t_p, wth + 49152, wtl + 49152, g_support_p, h2, N);
    spmm_kernel<64, 2><<<spmm_blocks, 256>>>(g_support_p, adj_col, adj_vals, g_t_p, N);

    // Layer 4: GEMM reads t3, fuses BN(layer2): writes h3 AND support = h3 @ W4
    gemm_tc<64, 32, 2><<<gemm_blocks, 256>>>(g_t_p, wth + 57344, wtl + 57344, g_support_p, h3, N);
    spmm_kernel<32, 3><<<spmm_blocks, 256>>>(g_support_p, adj_col, adj_vals, g_t_p, N);

    // Final norm for h4
    norm_kernel<32, 3><<<norm_blocks, 256>>>(g_t_p, h4, N);
}